// round 13
// baseline (speedup 1.0000x reference)
#include <cuda_runtime.h>
#include <stdint.h>

// PinPos forward: pin position = node position + pin offset (theta == 0).
// pos = [x_0..x_{N-1}, y_0..y_{N-1}]  (2N floats)
// out = [pinx_0..pinx_{P-1}, piny_0..piny_{P-1}]  (2P floats)
//
// R12 ncu: main kernel 44.1us, L1tex 74.8% (binding), L2 63.3%, DRAM 43.2%.
// The 8M 8B gathers (~32 wavefronts/warp-LDG) dominate L1tex. R13 changes:
//   * 8 pins/thread, all 8 gathers front-batched -> deeper MLP, fuller
//     L1tex wavefront queue across L2-hit latency.
//   * __ldcs/__stcs (evict-first) on all streaming traffic so the 16MB
//     interleaved posxy table stays fully L2-resident for the gathers.

#define MAX_NODES 2000000

// Scratch: interleaved (x,y) per node. 16 MB static device array.
__device__ float2 g_posxy[MAX_NODES];

__global__ __launch_bounds__(256)
void interleave_kernel(const float* __restrict__ pos, int num_nodes)
{
    const float* __restrict__ pos_y = pos + num_nodes;
    int i = (blockIdx.x * blockDim.x + threadIdx.x) * 4;

    if (i + 3 < num_nodes) {
        float4 x = __ldcs(reinterpret_cast<const float4*>(pos + i));
        float4 y = __ldcs(reinterpret_cast<const float4*>(pos_y + i));
        float4 lo = make_float4(x.x, y.x, x.y, y.y);
        float4 hi = make_float4(x.z, y.z, x.w, y.w);
        *reinterpret_cast<float4*>(&g_posxy[i])     = lo;
        *reinterpret_cast<float4*>(&g_posxy[i + 2]) = hi;
    } else {
        for (int j = i; j < num_nodes; ++j)
            g_posxy[j] = make_float2(pos[j], pos_y[j]);
    }
}

__global__ __launch_bounds__(256)
void pinpos_kernel(const float* __restrict__ offx,
                   const float* __restrict__ offy,
                   const int* __restrict__ p2n,
                   float* __restrict__ out,
                   int num_pins)
{
    float* __restrict__ out_y = out + num_pins;

    int i = (blockIdx.x * blockDim.x + threadIdx.x) * 8;

    if (i + 7 < num_pins) {
        // Front-batch all streaming loads (evict-first: never reused).
        int4   na  = __ldcs(reinterpret_cast<const int4*>(p2n + i));
        int4   nb  = __ldcs(reinterpret_cast<const int4*>(p2n + i + 4));
        float4 oxa = __ldcs(reinterpret_cast<const float4*>(offx + i));
        float4 oxb = __ldcs(reinterpret_cast<const float4*>(offx + i + 4));
        float4 oya = __ldcs(reinterpret_cast<const float4*>(offy + i));
        float4 oyb = __ldcs(reinterpret_cast<const float4*>(offy + i + 4));

        // 8 independent 8B gathers (posxy is L2-resident).
        float2 p0 = __ldg(&g_posxy[na.x]);
        float2 p1 = __ldg(&g_posxy[na.y]);
        float2 p2 = __ldg(&g_posxy[na.z]);
        float2 p3 = __ldg(&g_posxy[na.w]);
        float2 p4 = __ldg(&g_posxy[nb.x]);
        float2 p5 = __ldg(&g_posxy[nb.y]);
        float2 p6 = __ldg(&g_posxy[nb.z]);
        float2 p7 = __ldg(&g_posxy[nb.w]);

        float4 rxa = make_float4(p0.x + oxa.x, p1.x + oxa.y, p2.x + oxa.z, p3.x + oxa.w);
        float4 rxb = make_float4(p4.x + oxb.x, p5.x + oxb.y, p6.x + oxb.z, p7.x + oxb.w);
        float4 rya = make_float4(p0.y + oya.x, p1.y + oya.y, p2.y + oya.z, p3.y + oya.w);
        float4 ryb = make_float4(p4.y + oyb.x, p5.y + oyb.y, p6.y + oyb.z, p7.y + oyb.w);

        __stcs(reinterpret_cast<float4*>(out   + i),     rxa);
        __stcs(reinterpret_cast<float4*>(out   + i + 4), rxb);
        __stcs(reinterpret_cast<float4*>(out_y + i),     rya);
        __stcs(reinterpret_cast<float4*>(out_y + i + 4), ryb);
    } else {
        for (int j = i; j < num_pins; ++j) {
            float2 p = __ldg(&g_posxy[p2n[j]]);
            out[j]   = p.x + offx[j];
            out_y[j] = p.y + offy[j];
        }
    }
}

extern "C" void kernel_launch(void* const* d_in, const int* in_sizes, int n_in,
                              void* d_out, int out_size)
{
    // metadata order:
    // 0: pos (2*num_nodes float32)
    // 1: pin_offset_x (num_pins float32)
    // 2: pin_offset_y (num_pins float32)
    // 3: pin2node_map (num_pins int32 -- JAX x64 disabled)
    // 4: flat_node2pin_map (unused)
    // 5: flat_node2pin_start_map (unused)
    const float* pos  = (const float*)d_in[0];
    const float* offx = (const float*)d_in[1];
    const float* offy = (const float*)d_in[2];
    const int*   p2n  = (const int*)d_in[3];
    float* out = (float*)d_out;

    int num_nodes = in_sizes[0] / 2;
    int num_pins  = in_sizes[1];

    const int threads = 256;

    int nwork = (num_nodes + 3) / 4;
    int nblocks = (nwork + threads - 1) / threads;
    interleave_kernel<<<nblocks, threads>>>(pos, num_nodes);

    int pwork = (num_pins + 7) / 8;
    int pblocks = (pwork + threads - 1) / threads;
    pinpos_kernel<<<pblocks, threads>>>(offx, offy, p2n, out, num_pins);
}

// round 14
// speedup vs baseline: 1.0073x; 1.0073x over previous
#include <cuda_runtime.h>
#include <stdint.h>

// PinPos forward: pin position = node position + pin offset (theta == 0).
//
// R12: 4 pins/thread, regs=32, main 44.1us (L1tex 74.8% binding).
// R13 FAILED: 8 pins/thread but ptxas kept regs=32 -> serialized the
//   front-batched loads, MLP collapsed (issue 5.5->3.2%), 55.2us.
// R14: 8 pins/thread + __launch_bounds__(256, 4) so ptxas may use ~64 regs
//   and keep all 8 gathers + streaming loads in flight. Plain LDG for
//   streaming reads (drop __ldcs, confounded with R13 regression); __stcs
//   only on output stores.

#define MAX_NODES 2000000

// Scratch: interleaved (x,y) per node. 16 MB static device array.
__device__ float2 g_posxy[MAX_NODES];

__global__ __launch_bounds__(256)
void interleave_kernel(const float* __restrict__ pos, int num_nodes)
{
    const float* __restrict__ pos_y = pos + num_nodes;
    int i = (blockIdx.x * blockDim.x + threadIdx.x) * 8;

    if (i + 7 < num_nodes) {
        float4 xa = *reinterpret_cast<const float4*>(pos + i);
        float4 xb = *reinterpret_cast<const float4*>(pos + i + 4);
        float4 ya = *reinterpret_cast<const float4*>(pos_y + i);
        float4 yb = *reinterpret_cast<const float4*>(pos_y + i + 4);
        *reinterpret_cast<float4*>(&g_posxy[i])     = make_float4(xa.x, ya.x, xa.y, ya.y);
        *reinterpret_cast<float4*>(&g_posxy[i + 2]) = make_float4(xa.z, ya.z, xa.w, ya.w);
        *reinterpret_cast<float4*>(&g_posxy[i + 4]) = make_float4(xb.x, yb.x, xb.y, yb.y);
        *reinterpret_cast<float4*>(&g_posxy[i + 6]) = make_float4(xb.z, yb.z, xb.w, yb.w);
    } else {
        for (int j = i; j < num_nodes; ++j)
            g_posxy[j] = make_float2(pos[j], pos_y[j]);
    }
}

__global__ __launch_bounds__(256, 4)
void pinpos_kernel(const float* __restrict__ offx,
                   const float* __restrict__ offy,
                   const int* __restrict__ p2n,
                   float* __restrict__ out,
                   int num_pins)
{
    float* __restrict__ out_y = out + num_pins;

    int i = (blockIdx.x * blockDim.x + threadIdx.x) * 8;

    if (i + 7 < num_pins) {
        // Front-batch all streaming loads; needs ~56 live regs -> (256,4)
        // launch bounds keep ptxas from serializing them.
        int4   na  = *reinterpret_cast<const int4*>(p2n + i);
        int4   nb  = *reinterpret_cast<const int4*>(p2n + i + 4);
        float4 oxa = *reinterpret_cast<const float4*>(offx + i);
        float4 oxb = *reinterpret_cast<const float4*>(offx + i + 4);
        float4 oya = *reinterpret_cast<const float4*>(offy + i);
        float4 oyb = *reinterpret_cast<const float4*>(offy + i + 4);

        // 8 independent 8B gathers (posxy is L2-resident).
        float2 p0 = __ldg(&g_posxy[na.x]);
        float2 p1 = __ldg(&g_posxy[na.y]);
        float2 p2 = __ldg(&g_posxy[na.z]);
        float2 p3 = __ldg(&g_posxy[na.w]);
        float2 p4 = __ldg(&g_posxy[nb.x]);
        float2 p5 = __ldg(&g_posxy[nb.y]);
        float2 p6 = __ldg(&g_posxy[nb.z]);
        float2 p7 = __ldg(&g_posxy[nb.w]);

        float4 rxa = make_float4(p0.x + oxa.x, p1.x + oxa.y, p2.x + oxa.z, p3.x + oxa.w);
        float4 rxb = make_float4(p4.x + oxb.x, p5.x + oxb.y, p6.x + oxb.z, p7.x + oxb.w);
        float4 rya = make_float4(p0.y + oya.x, p1.y + oya.y, p2.y + oya.z, p3.y + oya.w);
        float4 ryb = make_float4(p4.y + oyb.x, p5.y + oyb.y, p6.y + oyb.z, p7.y + oyb.w);

        __stcs(reinterpret_cast<float4*>(out   + i),     rxa);
        __stcs(reinterpret_cast<float4*>(out   + i + 4), rxb);
        __stcs(reinterpret_cast<float4*>(out_y + i),     rya);
        __stcs(reinterpret_cast<float4*>(out_y + i + 4), ryb);
    } else {
        for (int j = i; j < num_pins; ++j) {
            float2 p = __ldg(&g_posxy[p2n[j]]);
            out[j]   = p.x + offx[j];
            out_y[j] = p.y + offy[j];
        }
    }
}

extern "C" void kernel_launch(void* const* d_in, const int* in_sizes, int n_in,
                              void* d_out, int out_size)
{
    // metadata order:
    // 0: pos (2*num_nodes float32)
    // 1: pin_offset_x (num_pins float32)
    // 2: pin_offset_y (num_pins float32)
    // 3: pin2node_map (num_pins int32 -- JAX x64 disabled)
    // 4: flat_node2pin_map (unused)
    // 5: flat_node2pin_start_map (unused)
    const float* pos  = (const float*)d_in[0];
    const float* offx = (const float*)d_in[1];
    const float* offy = (const float*)d_in[2];
    const int*   p2n  = (const int*)d_in[3];
    float* out = (float*)d_out;

    int num_nodes = in_sizes[0] / 2;
    int num_pins  = in_sizes[1];

    const int threads = 256;

    int nwork = (num_nodes + 7) / 8;
    int nblocks = (nwork + threads - 1) / threads;
    interleave_kernel<<<nblocks, threads>>>(pos, num_nodes);

    int pwork = (num_pins + 7) / 8;
    int pblocks = (pwork + threads - 1) / threads;
    pinpos_kernel<<<pblocks, threads>>>(offx, offy, p2n, out, num_pins);
}

// round 15
// speedup vs baseline: 1.0078x; 1.0005x over previous
#include <cuda_runtime.h>
#include <stdint.h>

// PinPos forward: pin position = node position + pin offset (theta == 0).
//
// R12: 4 pins/thread, regs=32, main 44.1us (L1tex 74.8% binding).
// R13 FAILED: 8 pins/thread but ptxas kept regs=32 -> serialized the
//   front-batched loads, MLP collapsed (issue 5.5->3.2%), 55.2us.
// R14: 8 pins/thread + __launch_bounds__(256, 4) so ptxas may use ~64 regs
//   and keep all 8 gathers + streaming loads in flight. Plain LDG for
//   streaming reads (drop __ldcs, confounded with R13 regression); __stcs
//   only on output stores.

#define MAX_NODES 2000000

// Scratch: interleaved (x,y) per node. 16 MB static device array.
__device__ float2 g_posxy[MAX_NODES];

__global__ __launch_bounds__(256)
void interleave_kernel(const float* __restrict__ pos, int num_nodes)
{
    const float* __restrict__ pos_y = pos + num_nodes;
    int i = (blockIdx.x * blockDim.x + threadIdx.x) * 8;

    if (i + 7 < num_nodes) {
        float4 xa = *reinterpret_cast<const float4*>(pos + i);
        float4 xb = *reinterpret_cast<const float4*>(pos + i + 4);
        float4 ya = *reinterpret_cast<const float4*>(pos_y + i);
        float4 yb = *reinterpret_cast<const float4*>(pos_y + i + 4);
        *reinterpret_cast<float4*>(&g_posxy[i])     = make_float4(xa.x, ya.x, xa.y, ya.y);
        *reinterpret_cast<float4*>(&g_posxy[i + 2]) = make_float4(xa.z, ya.z, xa.w, ya.w);
        *reinterpret_cast<float4*>(&g_posxy[i + 4]) = make_float4(xb.x, yb.x, xb.y, yb.y);
        *reinterpret_cast<float4*>(&g_posxy[i + 6]) = make_float4(xb.z, yb.z, xb.w, yb.w);
    } else {
        for (int j = i; j < num_nodes; ++j)
            g_posxy[j] = make_float2(pos[j], pos_y[j]);
    }
}

__global__ __launch_bounds__(256, 4)
void pinpos_kernel(const float* __restrict__ offx,
                   const float* __restrict__ offy,
                   const int* __restrict__ p2n,
                   float* __restrict__ out,
                   int num_pins)
{
    float* __restrict__ out_y = out + num_pins;

    int i = (blockIdx.x * blockDim.x + threadIdx.x) * 8;

    if (i + 7 < num_pins) {
        // Front-batch all streaming loads; needs ~56 live regs -> (256,4)
        // launch bounds keep ptxas from serializing them.
        int4   na  = *reinterpret_cast<const int4*>(p2n + i);
        int4   nb  = *reinterpret_cast<const int4*>(p2n + i + 4);
        float4 oxa = *reinterpret_cast<const float4*>(offx + i);
        float4 oxb = *reinterpret_cast<const float4*>(offx + i + 4);
        float4 oya = *reinterpret_cast<const float4*>(offy + i);
        float4 oyb = *reinterpret_cast<const float4*>(offy + i + 4);

        // 8 independent 8B gathers (posxy is L2-resident).
        float2 p0 = __ldg(&g_posxy[na.x]);
        float2 p1 = __ldg(&g_posxy[na.y]);
        float2 p2 = __ldg(&g_posxy[na.z]);
        float2 p3 = __ldg(&g_posxy[na.w]);
        float2 p4 = __ldg(&g_posxy[nb.x]);
        float2 p5 = __ldg(&g_posxy[nb.y]);
        float2 p6 = __ldg(&g_posxy[nb.z]);
        float2 p7 = __ldg(&g_posxy[nb.w]);

        float4 rxa = make_float4(p0.x + oxa.x, p1.x + oxa.y, p2.x + oxa.z, p3.x + oxa.w);
        float4 rxb = make_float4(p4.x + oxb.x, p5.x + oxb.y, p6.x + oxb.z, p7.x + oxb.w);
        float4 rya = make_float4(p0.y + oya.x, p1.y + oya.y, p2.y + oya.z, p3.y + oya.w);
        float4 ryb = make_float4(p4.y + oyb.x, p5.y + oyb.y, p6.y + oyb.z, p7.y + oyb.w);

        __stcs(reinterpret_cast<float4*>(out   + i),     rxa);
        __stcs(reinterpret_cast<float4*>(out   + i + 4), rxb);
        __stcs(reinterpret_cast<float4*>(out_y + i),     rya);
        __stcs(reinterpret_cast<float4*>(out_y + i + 4), ryb);
    } else {
        for (int j = i; j < num_pins; ++j) {
            float2 p = __ldg(&g_posxy[p2n[j]]);
            out[j]   = p.x + offx[j];
            out_y[j] = p.y + offy[j];
        }
    }
}

extern "C" void kernel_launch(void* const* d_in, const int* in_sizes, int n_in,
                              void* d_out, int out_size)
{
    // metadata order:
    // 0: pos (2*num_nodes float32)
    // 1: pin_offset_x (num_pins float32)
    // 2: pin_offset_y (num_pins float32)
    // 3: pin2node_map (num_pins int32 -- JAX x64 disabled)
    // 4: flat_node2pin_map (unused)
    // 5: flat_node2pin_start_map (unused)
    const float* pos  = (const float*)d_in[0];
    const float* offx = (const float*)d_in[1];
    const float* offy = (const float*)d_in[2];
    const int*   p2n  = (const int*)d_in[3];
    float* out = (float*)d_out;

    int num_nodes = in_sizes[0] / 2;
    int num_pins  = in_sizes[1];

    const int threads = 256;

    int nwork = (num_nodes + 7) / 8;
    int nblocks = (nwork + threads - 1) / threads;
    interleave_kernel<<<nblocks, threads>>>(pos, num_nodes);

    int pwork = (num_pins + 7) / 8;
    int pblocks = (pwork + threads - 1) / threads;
    pinpos_kernel<<<pblocks, threads>>>(offx, offy, p2n, out, num_pins);
}